// round 8
// baseline (speedup 1.0000x reference)
#include <cuda_runtime.h>
#include <cuda_bf16.h>
#include <math.h>
#include <stdint.h>

typedef unsigned long long u64;

#define BB   8
#define LL   1024
#define HHN  8
#define NQV  4
#define BHN  (BB*HHN)
#define CTX_ELEMS (BB*LL*HHN*64)
#define PI_F 3.14159274101257324f

// Q: Karatsuba bf16-split [bh][pos][96 bf16] = [r_hi|i_hi|s_hi|r_lo|i_lo|s_lo]
__device__ __nv_bfloat16 g_qA[(size_t)BHN * 1024 * 96];
// K interleaved: [bh][s][24 u64], u64_j = hi_u32(j) | lo_u32(j)<<32, j = g*8 + kpair
__device__ u64 g_kBi[(size_t)BHN * 1024 * 24];
// V interleaved: [bh][d 0..63][s-pair 0..511] u64 = (hi bf16x2 | lo bf16x2 << 32)
__device__ u64 g_vTi[(size_t)BHN * 64 * 512];

// ---------------- helpers ----------------
__device__ __forceinline__ void mma_bf16(float4& c, const uint32_t a[4],
                                         uint32_t b0, uint32_t b1) {
    asm("mma.sync.aligned.m16n8k16.row.col.f32.bf16.bf16.f32 "
        "{%0,%1,%2,%3},{%4,%5,%6,%7},{%8,%9},{%0,%1,%2,%3};"
        : "+f"(c.x), "+f"(c.y), "+f"(c.z), "+f"(c.w)
        : "r"(a[0]), "r"(a[1]), "r"(a[2]), "r"(a[3]), "r"(b0), "r"(b1));
}
__device__ __forceinline__ uint32_t bfpack(float a, float b) {   // a->low, b->high
    uint32_t r; asm("cvt.rn.bf16x2.f32 %0, %1, %2;" : "=r"(r) : "f"(b), "f"(a)); return r;
}
__device__ __forceinline__ float bflowf(uint32_t v)  { return __uint_as_float(v << 16); }
__device__ __forceinline__ float bfhighf(uint32_t v) { return __uint_as_float(v & 0xFFFF0000u); }
__device__ __forceinline__ void cpa16s(uint32_t saddr, const void* gsrc) {
    asm volatile("cp.async.cg.shared.global [%0], [%1], 16;" :: "r"(saddr), "l"(gsrc));
}
__device__ __forceinline__ void cpa_commit() {
    asm volatile("cp.async.commit_group;" ::: "memory");
}
template<int N>
__device__ __forceinline__ void cpa_wait() {
    asm volatile("cp.async.wait_group %0;" :: "n"(N) : "memory");
}
__device__ __forceinline__ uint32_t s2u(const void* p) {
    return (uint32_t)__cvta_generic_to_shared(p);
}

// ======================================================================
// Prep: Q encode (0..255), K encode (256..511), V interleave (512..767)
// ======================================================================
#define PREP_SMEM (128 * 264 * 2)
__global__ void __launch_bounds__(256) prep_kernel(
    const float* __restrict__ qin, const float* __restrict__ kin,
    const float* __restrict__ vin,
    const float* __restrict__ wq, const float* __restrict__ bq,
    const float* __restrict__ wk, const float* __restrict__ bk)
{
    extern __shared__ __nv_bfloat16 smA[];
    __shared__ float sw[NQV * 64];
    __shared__ float sb[NQV];
    const int bid = blockIdx.x;
    const int tid = threadIdx.x;

    if (bid >= 512) {   // ---- V transpose + bf16 split + interleave ----
        int vb = bid - 512;
        int bh = vb >> 2, sc0 = (vb & 3) * 256;
        int b = bh >> 3, h = bh & 7;
        const float4* vg = (const float4*)vin;
#pragma unroll
        for (int j = 0; j < 16; j++) {
            int i = tid + j * 256;
            int s = i >> 4, d4 = i & 15;
            float4 xv = vg[((size_t)((b * 1024 + sc0 + s) * 8 + h)) * 16 + d4];
            const float* px = &xv.x;
#pragma unroll
            for (int jj = 0; jj < 4; jj++) {
                int d = d4 * 4 + jj;
                float val = px[jj];
                __nv_bfloat16 hb = __float2bfloat16(val);
                smA[d * 264 + s] = hb;
                smA[(64 + d) * 264 + s] = __float2bfloat16(val - __bfloat162float(hb));
            }
        }
        __syncthreads();
        u64* dst = g_vTi + (size_t)bh * 32768;
#pragma unroll
        for (int j = 0; j < 8; j++) {
            int i = tid + j * 256;
            int row = i >> 5, cc = i & 31;
            uint4 hv = *(const uint4*)&smA[row * 264 + cc * 8];
            uint4 lv = *(const uint4*)&smA[(64 + row) * 264 + cc * 8];
            size_t di = (size_t)row * 512 + (sc0 >> 1) + cc * 4;
            *(ulonglong2*)&dst[di] =
                make_ulonglong2(hv.x | ((u64)lv.x << 32), hv.y | ((u64)lv.y << 32));
            *(ulonglong2*)&dst[di + 2] =
                make_ulonglong2(hv.z | ((u64)lv.z << 32), hv.w | ((u64)lv.w << 32));
        }
        return;
    }

    const int isK = (bid >= 256);
    const float* x = isK ? kin : qin;
    const float* w = isK ? wk : wq;
    const float* bias = isK ? bk : bq;
    if (tid < NQV * 64) sw[tid] = w[tid];
    if (tid < NQV) sb[tid] = bias[tid];
    __syncthreads();

    int n  = (bid & 255) * 256 + tid;
    int bh = n >> 10, loc = n & 1023;
    int b = bh >> 3, h = bh & 7;
    const float* xr = x + (size_t)((b * 1024 + loc) * HHN + h) * 64;

    float th[NQV];
#pragma unroll
    for (int j = 0; j < NQV; j++) th[j] = sb[j];
#pragma unroll 4
    for (int d = 0; d < 64; d += 4) {
        float4 xv = *(const float4*)(xr + d);
#pragma unroll
        for (int j = 0; j < NQV; j++) {
            th[j] += xv.x * sw[j * 64 + d]     + xv.y * sw[j * 64 + d + 1]
                   + xv.z * sw[j * 64 + d + 2] + xv.w * sw[j * 64 + d + 3];
        }
    }
#pragma unroll
    for (int j = 0; j < NQV; j++) th[j] = tanhf(th[j]) * PI_F;
    float bt[3];
#pragma unroll
    for (int p = 0; p < 3; p++) bt[p] = th[p] * th[p + 1];

    float co[16], si[16];
#pragma unroll
    for (int d = 0; d < 16; d++) {
        float a = 0.f;
        a += ((d >> 3) & 1) ? -th[0] : th[0];
        a += ((d >> 2) & 1) ? -th[1] : th[1];
        a += ((d >> 1) & 1) ? -th[2] : th[2];
        a += ( d       & 1) ? -th[3] : th[3];
        a += (((d >> 3) ^ (d >> 2)) & 1) ? -bt[0] : bt[0];
        a += (((d >> 2) ^ (d >> 1)) & 1) ? -bt[1] : bt[1];
        a += (((d >> 1) ^  d      ) & 1) ? -bt[2] : bt[2];
        sincosf(-0.5f * a, &si[d], &co[d]);
    }
    float re[16], im[16];
#pragma unroll
    for (int d = 0; d < 16; d++) { re[d] = co[d]; im[d] = si[d]; }
#pragma unroll
    for (int hs = 1; hs < 16; hs <<= 1) {
#pragma unroll
        for (int i = 0; i < 16; i++) {
            if ((i & hs) == 0) {
                int j2 = i | hs;
                float ar = re[i], ai = im[i], br = re[j2], bi = im[j2];
                re[i] = ar + br;  im[i] = ai + bi;
                re[j2] = ar - br; im[j2] = ai - bi;
            }
        }
    }

    float fr[16], fi[16], fs[16];
#pragma unroll
    for (int d = 0; d < 16; d++) {
        float tr = re[d] * 0.0625f, ti = im[d] * 0.0625f;
        fr[d] = tr * co[d] - ti * si[d];
        fi[d] = tr * si[d] + ti * co[d];
        fs[d] = isK ? (fr[d] - fi[d]) : (fr[d] + fi[d]);
    }

    uint32_t uw[48];
#pragma unroll
    for (int j = 0; j < 8; j++) {
        uint32_t hp;
        hp = bfpack(fr[2*j], fr[2*j+1]);
        uw[j] = hp;
        uw[24 + j] = bfpack(fr[2*j] - bflowf(hp), fr[2*j+1] - bfhighf(hp));
        hp = bfpack(fi[2*j], fi[2*j+1]);
        uw[8 + j] = hp;
        uw[32 + j] = bfpack(fi[2*j] - bflowf(hp), fi[2*j+1] - bfhighf(hp));
        hp = bfpack(fs[2*j], fs[2*j+1]);
        uw[16 + j] = hp;
        uw[40 + j] = bfpack(fs[2*j] - bflowf(hp), fs[2*j+1] - bfhighf(hp));
    }
    if (!isK) {
        uint4* o4 = (uint4*)(g_qA + (size_t)n * 96);
#pragma unroll
        for (int q = 0; q < 12; q++)
            o4[q] = make_uint4(uw[4*q], uw[4*q+1], uw[4*q+2], uw[4*q+3]);
    } else {
        ulonglong2* o2 = (ulonglong2*)(g_kBi + (size_t)n * 24);
#pragma unroll
        for (int j = 0; j < 12; j++)
            o2[j] = make_ulonglong2((u64)uw[2*j]   | ((u64)uw[24 + 2*j]   << 32),
                                    (u64)uw[2*j+1] | ((u64)uw[24 + 2*j+1] << 32));
    }
}

// ======================================================================
// Fused attention: hoisted addressing, u64 operands everywhere, occ 2.
// ======================================================================
#define SC_STRIDE 516                       // u64 per score row (conflict-free)
#define SC_U64 (16 * SC_STRIDE)             // 8256
#define WARP_U64 576                        // per-warp buffer (V: 2 x 288)
#define KSTG 224                            // K stage size (8 rows x 28 u64)
#define SMEM_BYTES ((SC_U64 + 8 * WARP_U64) * 8)   // 102912

__global__ void __launch_bounds__(256, 2) attn_fused(float* __restrict__ out)
{
    extern __shared__ u64 sm64[];
    u64* scores = sm64;                      // [16][516]
    __shared__ float sred[8][16];
    __shared__ float sinv[16];

    const int bh = blockIdx.y;
    const int l0 = blockIdx.x * 16;
    const int b = bh >> 3, h = bh & 7;
    const int tid = threadIdx.x;
    const int w = tid >> 5, lane = tid & 31;
    const int gr = lane >> 2, ctg = lane & 3;

    u64* wbuf = sm64 + SC_U64 + w * WARP_U64;
    const uint32_t wsa = s2u(wbuf);          // shared byte address of warp buffer

    // resident bf16 Q fragments
    uint32_t Ah[3][4], Al[3][4];
    {
        const uint32_t* qa = (const uint32_t*)g_qA + (size_t)bh * 49152 + (size_t)l0 * 48;
#pragma unroll
        for (int g = 0; g < 3; g++) {
            Ah[g][0] = qa[gr * 48 + g * 8 + ctg];
            Ah[g][1] = qa[(gr + 8) * 48 + g * 8 + ctg];
            Ah[g][2] = qa[gr * 48 + g * 8 + 4 + ctg];
            Ah[g][3] = qa[(gr + 8) * 48 + g * 8 + 4 + ctg];
            Al[g][0] = qa[gr * 48 + 24 + g * 8 + ctg];
            Al[g][1] = qa[(gr + 8) * 48 + 24 + g * 8 + ctg];
            Al[g][2] = qa[gr * 48 + 24 + g * 8 + 4 + ctg];
            Al[g][3] = qa[(gr + 8) * 48 + 24 + g * 8 + 4 + ctg];
        }
    }

    // ---- phase A: hoisted staging addresses ----
    const u64* kg = g_kBi + (size_t)bh * 24576;
    const int r0 = lane / 12, f0 = lane - r0 * 12;
    const int r1 = (lane + 32) / 12, f1 = (lane + 32) - r1 * 12;
    const int r2 = (lane + 64) / 12, f2 = (lane + 64) - r2 * 12;
    const uint32_t kd0 = wsa + (uint32_t)(r0 * 28 + f0 * 2) * 8;
    const uint32_t kd1 = wsa + (uint32_t)(r1 * 28 + f1 * 2) * 8;
    const uint32_t kd2 = wsa + (uint32_t)(r2 * 28 + f2 * 2) * 8;
    const u64* ks0 = kg + (w * 8 + r0) * 24 + f0 * 2;
    const u64* ks1 = kg + (w * 8 + r1) * 24 + f1 * 2;
    const u64* ks2 = kg + (w * 8 + r2) * 24 + f2 * 2;

    auto issueK = [&](int c) {
        const uint32_t so = (c & 1) ? (uint32_t)(KSTG * 8) : 0u;
        const size_t go = (size_t)c * 1536;
        cpa16s(kd0 + so, ks0 + go);
        cpa16s(kd1 + so, ks1 + go);
        cpa16s(kd2 + so, ks2 + go);
        cpa_commit();
    };

    u64* srow0 = scores + gr * SC_STRIDE + w * 4 + ctg;
    u64* srow1 = srow0 + 8 * SC_STRIDE;
    const u64* bb0 = wbuf + gr * 28;

    float rs0 = 0.f, rs1 = 0.f;
    issueK(0);
    issueK(1);

#pragma unroll 1
    for (int c = 0; c < 16; c++) {
        if (c < 15) cpa_wait<1>(); else cpa_wait<0>();
        __syncwarp();
        const u64* bb = bb0 + ((c & 1) ? KSTG : 0);

        u64 B0[3], B1[3];
#pragma unroll
        for (int g = 0; g < 3; g++) {
            B0[g] = bb[g * 8 + ctg];
            B1[g] = bb[g * 8 + 4 + ctg];
        }
        __syncwarp();
        if (c < 14) issueK(c + 2);

        float4 acc[3];
#pragma unroll
        for (int g = 0; g < 3; g++) acc[g] = make_float4(0.f, 0.f, 0.f, 0.f);
#pragma unroll
        for (int g = 0; g < 3; g++) {
            uint32_t bh0 = (uint32_t)B0[g], bh1 = (uint32_t)B1[g];
            uint32_t bl0 = (uint32_t)(B0[g] >> 32), bl1 = (uint32_t)(B1[g] >> 32);
            mma_bf16(acc[g], Ah[g], bh0, bh1);
            mma_bf16(acc[g], Ah[g], bl0, bl1);
            mma_bf16(acc[g], Al[g], bh0, bh1);
        }

        float4 c1 = acc[0], c2 = acc[1], c3 = acc[2];
        float fr, fi, p0, p1, p2, p3;
        fr = c1.x + c2.x; fi = c3.x - c1.x + c2.x; p0 = fr * fr + fi * fi;
        fr = c1.y + c2.y; fi = c3.y - c1.y + c2.y; p1 = fr * fr + fi * fi;
        fr = c1.z + c2.z; fi = c3.z - c1.z + c2.z; p2 = fr * fr + fi * fi;
        fr = c1.w + c2.w; fi = c3.w - c1.w + c2.w; p3 = fr * fr + fi * fi;

        uint32_t h01 = bfpack(p0, p1);
        uint32_t h23 = bfpack(p2, p3);
        uint32_t l01 = bfpack(p0 - bflowf(h01), p1 - bfhighf(h01));
        uint32_t l23 = bfpack(p2 - bflowf(h23), p3 - bfhighf(h23));
        srow0[c * 32] = (u64)h01 | ((u64)l01 << 32);
        srow1[c * 32] = (u64)h23 | ((u64)l23 << 32);
        rs0 += p0 + p1; rs1 += p2 + p3;
    }

    // ---- rowsums ----
    rs0 += __shfl_xor_sync(0xFFFFFFFFu, rs0, 1);
    rs0 += __shfl_xor_sync(0xFFFFFFFFu, rs0, 2);
    rs1 += __shfl_xor_sync(0xFFFFFFFFu, rs1, 1);
    rs1 += __shfl_xor_sync(0xFFFFFFFFu, rs1, 2);
    if (ctg == 0) { sred[w][gr] = rs0; sred[w][gr + 8] = rs1; }
    __syncthreads();

    // ---- V pipeline (hoisted addresses), prologue overlaps weights write ----
    const u64* vt = g_vTi + (size_t)bh * 32768;
    const int vr0 = lane >> 4, vf0 = lane & 15;    // t tiles: r = vr0 + 2t
    uint32_t vd[4];
    const u64* vs[4];
#pragma unroll
    for (int t = 0; t < 4; t++) {
        int r = vr0 + 2 * t;
        vd[t] = wsa + (uint32_t)(r * 36 + vf0 * 2) * 8;
        vs[t] = vt + (size_t)(w * 8 + r) * 512 + vf0 * 2;
    }
    auto issueV = [&](int c) {
        const uint32_t so = (c & 1) ? (uint32_t)(288 * 8) : 0u;
        const int go = c * 32;
        cpa16s(vd[0] + so, vs[0] + go);
        cpa16s(vd[1] + so, vs[1] + go);
        cpa16s(vd[2] + so, vs[2] + go);
        cpa16s(vd[3] + so, vs[3] + go);
        cpa_commit();
    };
    issueV(0);
    issueV(1);

    if (tid < 16) {
        float s = 0.f;
#pragma unroll
        for (int ww = 0; ww < 8; ww++) s += sred[ww][tid];
        sinv[tid] = 1.0f / (s + 1e-6f);
    }
    __syncthreads();

    // ---- phase B: single normalized weights pass ----
    {
        float2* wout = (float2*)(out + (size_t)CTX_ELEMS + ((size_t)bh * 1024 + l0) * 1024);
#pragma unroll 8
        for (int i = tid; i < 8192; i += 256) {
            int row = i >> 9, pr = i & 511;
            u64 v = scores[row * SC_STRIDE + pr];
            uint32_t hv = (uint32_t)v, lv = (uint32_t)(v >> 32);
            float iv = sinv[row];
            wout[(size_t)row * 512 + pr] =
                make_float2((bflowf(hv) + bflowf(lv)) * iv,
                            (bfhighf(hv) + bfhighf(lv)) * iv);
        }
    }

    // ---- phase C: context (warp = d-octet) ----
    float4 aHH = make_float4(0.f, 0.f, 0.f, 0.f);
    float4 aHL = make_float4(0.f, 0.f, 0.f, 0.f);
    float4 aLH = make_float4(0.f, 0.f, 0.f, 0.f);
    const u64* vbb0 = wbuf + gr * 36;
    const u64* sC0 = scores + gr * SC_STRIDE + ctg;
    const u64* sC1 = sC0 + 8 * SC_STRIDE;

#pragma unroll 1
    for (int c = 0; c < 16; c++) {
        if (c < 15) cpa_wait<1>(); else cpa_wait<0>();
        __syncwarp();
        const u64* vbb = vbb0 + ((c & 1) ? 288 : 0);

        u64 vv[4][2];
#pragma unroll
        for (int kk = 0; kk < 4; kk++) {
            vv[kk][0] = vbb[kk * 8 + ctg];
            vv[kk][1] = vbb[kk * 8 + 4 + ctg];
        }
        __syncwarp();
        if (c < 14) issueV(c + 2);

#pragma unroll
        for (int kk = 0; kk < 4; kk++) {
            int base = c * 32 + kk * 8;
            u64 s0 = sC0[base];
            u64 s1 = sC1[base];
            u64 s2 = sC0[base + 4];
            u64 s3 = sC1[base + 4];
            uint32_t aH[4] = {(uint32_t)s0, (uint32_t)s1, (uint32_t)s2, (uint32_t)s3};
            uint32_t aL[4] = {(uint32_t)(s0 >> 32), (uint32_t)(s1 >> 32),
                              (uint32_t)(s2 >> 32), (uint32_t)(s3 >> 32)};
            uint32_t bh0 = (uint32_t)vv[kk][0], bh1 = (uint32_t)vv[kk][1];
            uint32_t bl0 = (uint32_t)(vv[kk][0] >> 32), bl1 = (uint32_t)(vv[kk][1] >> 32);

            mma_bf16(aHH, aH, bh0, bh1);
            mma_bf16(aHL, aH, bl0, bl1);
            mma_bf16(aLH, aL, bh0, bh1);
        }
    }

    {
        float4 cc = make_float4(aHH.x + aHL.x + aLH.x, aHH.y + aHL.y + aLH.y,
                                aHH.z + aHL.z + aLH.z, aHH.w + aHL.w + aLH.w);
        float ivt = sinv[gr], ivb = sinv[gr + 8];
        int lt = l0 + gr, lb = lt + 8;
        int d = w * 8 + 2 * ctg;
        *(float2*)&out[((size_t)((b * 1024 + lt) * 8 + h)) * 64 + d]
            = make_float2(cc.x * ivt, cc.y * ivt);
        *(float2*)&out[((size_t)((b * 1024 + lb) * 8 + h)) * 64 + d]
            = make_float2(cc.z * ivb, cc.w * ivb);
    }
}

// ======================================================================
extern "C" void kernel_launch(void* const* d_in, const int* in_sizes, int n_in,
                              void* d_out, int out_size)
{
    (void)in_sizes; (void)n_in; (void)out_size;
    const float* q  = (const float*)d_in[0];
    const float* k  = (const float*)d_in[1];
    const float* v  = (const float*)d_in[2];
    const float* wq = (const float*)d_in[3];
    const float* bq = (const float*)d_in[4];
    const float* wk = (const float*)d_in[5];
    const float* bk = (const float*)d_in[6];
    float* out = (float*)d_out;

    cudaFuncSetAttribute(prep_kernel, cudaFuncAttributeMaxDynamicSharedMemorySize, PREP_SMEM);
    cudaFuncSetAttribute(attn_fused,  cudaFuncAttributeMaxDynamicSharedMemorySize, SMEM_BYTES);

    prep_kernel<<<768, 256, PREP_SMEM>>>(q, k, v, wq, bq, wk, bk);
    attn_fused<<<dim3(64, BHN), 256, SMEM_BYTES>>>(out);
}

// round 9
// speedup vs baseline: 1.0001x; 1.0001x over previous
#include <cuda_runtime.h>
#include <cuda_bf16.h>
#include <math.h>
#include <stdint.h>

typedef unsigned long long u64;

#define BB   8
#define LL   1024
#define HHN  8
#define NQV  4
#define BHN  (BB*HHN)
#define CTX_ELEMS (BB*LL*HHN*64)
#define PI_F 3.14159274101257324f

// Q: Karatsuba bf16-split [bh][pos][96 bf16] = [r_hi|i_hi|s_hi|r_lo|i_lo|s_lo]
__device__ __nv_bfloat16 g_qA[(size_t)BHN * 1024 * 96];
// K interleaved: [bh][s][24 u64], u64_j = hi_u32(j) | lo_u32(j)<<32, j = g*8 + kpair
__device__ u64 g_kBi[(size_t)BHN * 1024 * 24];
// V interleaved: [bh][d 0..63][s-pair 0..511] u64 = (hi bf16x2 | lo bf16x2 << 32)
__device__ u64 g_vTi[(size_t)BHN * 64 * 512];

// ---------------- helpers ----------------
__device__ __forceinline__ void mma_bf16(float4& c, const uint32_t a[4],
                                         uint32_t b0, uint32_t b1) {
    asm("mma.sync.aligned.m16n8k16.row.col.f32.bf16.bf16.f32 "
        "{%0,%1,%2,%3},{%4,%5,%6,%7},{%8,%9},{%0,%1,%2,%3};"
        : "+f"(c.x), "+f"(c.y), "+f"(c.z), "+f"(c.w)
        : "r"(a[0]), "r"(a[1]), "r"(a[2]), "r"(a[3]), "r"(b0), "r"(b1));
}
__device__ __forceinline__ uint32_t bfpack(float a, float b) {   // a->low, b->high
    uint32_t r; asm("cvt.rn.bf16x2.f32 %0, %1, %2;" : "=r"(r) : "f"(b), "f"(a)); return r;
}
__device__ __forceinline__ float bflowf(uint32_t v)  { return __uint_as_float(v << 16); }
__device__ __forceinline__ float bfhighf(uint32_t v) { return __uint_as_float(v & 0xFFFF0000u); }
__device__ __forceinline__ void cpa16s(uint32_t saddr, const void* gsrc) {
    asm volatile("cp.async.cg.shared.global [%0], [%1], 16;" :: "r"(saddr), "l"(gsrc));
}
__device__ __forceinline__ void cpa_commit() {
    asm volatile("cp.async.commit_group;" ::: "memory");
}
template<int N>
__device__ __forceinline__ void cpa_wait() {
    asm volatile("cp.async.wait_group %0;" :: "n"(N) : "memory");
}
__device__ __forceinline__ uint32_t s2u(const void* p) {
    return (uint32_t)__cvta_generic_to_shared(p);
}

// ======================================================================
// Prep: Q encode (0..255), K encode (256..511), V interleave (512..767)
// ======================================================================
#define PREP_SMEM (128 * 264 * 2)
__global__ void __launch_bounds__(256) prep_kernel(
    const float* __restrict__ qin, const float* __restrict__ kin,
    const float* __restrict__ vin,
    const float* __restrict__ wq, const float* __restrict__ bq,
    const float* __restrict__ wk, const float* __restrict__ bk)
{
    extern __shared__ __nv_bfloat16 smA[];
    __shared__ float sw[NQV * 64];
    __shared__ float sb[NQV];
    const int bid = blockIdx.x;
    const int tid = threadIdx.x;

    if (bid >= 512) {   // ---- V transpose + bf16 split + interleave ----
        int vb = bid - 512;
        int bh = vb >> 2, sc0 = (vb & 3) * 256;
        int b = bh >> 3, h = bh & 7;
        const float4* vg = (const float4*)vin;
#pragma unroll
        for (int j = 0; j < 16; j++) {
            int i = tid + j * 256;
            int s = i >> 4, d4 = i & 15;
            float4 xv = vg[((size_t)((b * 1024 + sc0 + s) * 8 + h)) * 16 + d4];
            const float* px = &xv.x;
#pragma unroll
            for (int jj = 0; jj < 4; jj++) {
                int d = d4 * 4 + jj;
                float val = px[jj];
                __nv_bfloat16 hb = __float2bfloat16(val);
                smA[d * 264 + s] = hb;
                smA[(64 + d) * 264 + s] = __float2bfloat16(val - __bfloat162float(hb));
            }
        }
        __syncthreads();
        u64* dst = g_vTi + (size_t)bh * 32768;
#pragma unroll
        for (int j = 0; j < 8; j++) {
            int i = tid + j * 256;
            int row = i >> 5, cc = i & 31;
            uint4 hv = *(const uint4*)&smA[row * 264 + cc * 8];
            uint4 lv = *(const uint4*)&smA[(64 + row) * 264 + cc * 8];
            size_t di = (size_t)row * 512 + (sc0 >> 1) + cc * 4;
            *(ulonglong2*)&dst[di] =
                make_ulonglong2(hv.x | ((u64)lv.x << 32), hv.y | ((u64)lv.y << 32));
            *(ulonglong2*)&dst[di + 2] =
                make_ulonglong2(hv.z | ((u64)lv.z << 32), hv.w | ((u64)lv.w << 32));
        }
        return;
    }

    const int isK = (bid >= 256);
    const float* x = isK ? kin : qin;
    const float* w = isK ? wk : wq;
    const float* bias = isK ? bk : bq;
    if (tid < NQV * 64) sw[tid] = w[tid];
    if (tid < NQV) sb[tid] = bias[tid];
    __syncthreads();

    int n  = (bid & 255) * 256 + tid;
    int bh = n >> 10, loc = n & 1023;
    int b = bh >> 3, h = bh & 7;
    const float* xr = x + (size_t)((b * 1024 + loc) * HHN + h) * 64;

    float th[NQV];
#pragma unroll
    for (int j = 0; j < NQV; j++) th[j] = sb[j];
#pragma unroll 4
    for (int d = 0; d < 64; d += 4) {
        float4 xv = *(const float4*)(xr + d);
#pragma unroll
        for (int j = 0; j < NQV; j++) {
            th[j] += xv.x * sw[j * 64 + d]     + xv.y * sw[j * 64 + d + 1]
                   + xv.z * sw[j * 64 + d + 2] + xv.w * sw[j * 64 + d + 3];
        }
    }
#pragma unroll
    for (int j = 0; j < NQV; j++) th[j] = tanhf(th[j]) * PI_F;
    float bt[3];
#pragma unroll
    for (int p = 0; p < 3; p++) bt[p] = th[p] * th[p + 1];

    float co[16], si[16];
#pragma unroll
    for (int d = 0; d < 16; d++) {
        float a = 0.f;
        a += ((d >> 3) & 1) ? -th[0] : th[0];
        a += ((d >> 2) & 1) ? -th[1] : th[1];
        a += ((d >> 1) & 1) ? -th[2] : th[2];
        a += ( d       & 1) ? -th[3] : th[3];
        a += (((d >> 3) ^ (d >> 2)) & 1) ? -bt[0] : bt[0];
        a += (((d >> 2) ^ (d >> 1)) & 1) ? -bt[1] : bt[1];
        a += (((d >> 1) ^  d      ) & 1) ? -bt[2] : bt[2];
        sincosf(-0.5f * a, &si[d], &co[d]);
    }
    float re[16], im[16];
#pragma unroll
    for (int d = 0; d < 16; d++) { re[d] = co[d]; im[d] = si[d]; }
#pragma unroll
    for (int hs = 1; hs < 16; hs <<= 1) {
#pragma unroll
        for (int i = 0; i < 16; i++) {
            if ((i & hs) == 0) {
                int j2 = i | hs;
                float ar = re[i], ai = im[i], br = re[j2], bi = im[j2];
                re[i] = ar + br;  im[i] = ai + bi;
                re[j2] = ar - br; im[j2] = ai - bi;
            }
        }
    }

    float fr[16], fi[16], fs[16];
#pragma unroll
    for (int d = 0; d < 16; d++) {
        float tr = re[d] * 0.0625f, ti = im[d] * 0.0625f;
        fr[d] = tr * co[d] - ti * si[d];
        fi[d] = tr * si[d] + ti * co[d];
        fs[d] = isK ? (fr[d] - fi[d]) : (fr[d] + fi[d]);
    }

    uint32_t uw[48];
#pragma unroll
    for (int j = 0; j < 8; j++) {
        uint32_t hp;
        hp = bfpack(fr[2*j], fr[2*j+1]);
        uw[j] = hp;
        uw[24 + j] = bfpack(fr[2*j] - bflowf(hp), fr[2*j+1] - bfhighf(hp));
        hp = bfpack(fi[2*j], fi[2*j+1]);
        uw[8 + j] = hp;
        uw[32 + j] = bfpack(fi[2*j] - bflowf(hp), fi[2*j+1] - bfhighf(hp));
        hp = bfpack(fs[2*j], fs[2*j+1]);
        uw[16 + j] = hp;
        uw[40 + j] = bfpack(fs[2*j] - bflowf(hp), fs[2*j+1] - bfhighf(hp));
    }
    if (!isK) {
        uint4* o4 = (uint4*)(g_qA + (size_t)n * 96);
#pragma unroll
        for (int q = 0; q < 12; q++)
            o4[q] = make_uint4(uw[4*q], uw[4*q+1], uw[4*q+2], uw[4*q+3]);
    } else {
        ulonglong2* o2 = (ulonglong2*)(g_kBi + (size_t)n * 24);
#pragma unroll
        for (int j = 0; j < 12; j++)
            o2[j] = make_ulonglong2((u64)uw[2*j]   | ((u64)uw[24 + 2*j]   << 32),
                                    (u64)uw[2*j+1] | ((u64)uw[24 + 2*j+1] << 32));
    }
}

// ======================================================================
// Fused attention: hoisted addressing, u64 operands everywhere, occ 2.
// ======================================================================
#define SC_STRIDE 516                       // u64 per score row (conflict-free)
#define SC_U64 (16 * SC_STRIDE)             // 8256
#define WARP_U64 576                        // per-warp buffer (V: 2 x 288)
#define KSTG 224                            // K stage size (8 rows x 28 u64)
#define SMEM_BYTES ((SC_U64 + 8 * WARP_U64) * 8)   // 102912

__global__ void __launch_bounds__(256, 2) attn_fused(float* __restrict__ out)
{
    extern __shared__ u64 sm64[];
    u64* scores = sm64;                      // [16][516]
    __shared__ float sred[8][16];
    __shared__ float sinv[16];

    const int bh = blockIdx.y;
    const int l0 = blockIdx.x * 16;
    const int b = bh >> 3, h = bh & 7;
    const int tid = threadIdx.x;
    const int w = tid >> 5, lane = tid & 31;
    const int gr = lane >> 2, ctg = lane & 3;

    u64* wbuf = sm64 + SC_U64 + w * WARP_U64;
    const uint32_t wsa = s2u(wbuf);          // shared byte address of warp buffer

    // resident bf16 Q fragments
    uint32_t Ah[3][4], Al[3][4];
    {
        const uint32_t* qa = (const uint32_t*)g_qA + (size_t)bh * 49152 + (size_t)l0 * 48;
#pragma unroll
        for (int g = 0; g < 3; g++) {
            Ah[g][0] = qa[gr * 48 + g * 8 + ctg];
            Ah[g][1] = qa[(gr + 8) * 48 + g * 8 + ctg];
            Ah[g][2] = qa[gr * 48 + g * 8 + 4 + ctg];
            Ah[g][3] = qa[(gr + 8) * 48 + g * 8 + 4 + ctg];
            Al[g][0] = qa[gr * 48 + 24 + g * 8 + ctg];
            Al[g][1] = qa[(gr + 8) * 48 + 24 + g * 8 + ctg];
            Al[g][2] = qa[gr * 48 + 24 + g * 8 + 4 + ctg];
            Al[g][3] = qa[(gr + 8) * 48 + 24 + g * 8 + 4 + ctg];
        }
    }

    // ---- phase A: hoisted staging addresses ----
    const u64* kg = g_kBi + (size_t)bh * 24576;
    const int r0 = lane / 12, f0 = lane - r0 * 12;
    const int r1 = (lane + 32) / 12, f1 = (lane + 32) - r1 * 12;
    const int r2 = (lane + 64) / 12, f2 = (lane + 64) - r2 * 12;
    const uint32_t kd0 = wsa + (uint32_t)(r0 * 28 + f0 * 2) * 8;
    const uint32_t kd1 = wsa + (uint32_t)(r1 * 28 + f1 * 2) * 8;
    const uint32_t kd2 = wsa + (uint32_t)(r2 * 28 + f2 * 2) * 8;
    const u64* ks0 = kg + (w * 8 + r0) * 24 + f0 * 2;
    const u64* ks1 = kg + (w * 8 + r1) * 24 + f1 * 2;
    const u64* ks2 = kg + (w * 8 + r2) * 24 + f2 * 2;

    auto issueK = [&](int c) {
        const uint32_t so = (c & 1) ? (uint32_t)(KSTG * 8) : 0u;
        const size_t go = (size_t)c * 1536;
        cpa16s(kd0 + so, ks0 + go);
        cpa16s(kd1 + so, ks1 + go);
        cpa16s(kd2 + so, ks2 + go);
        cpa_commit();
    };

    u64* srow0 = scores + gr * SC_STRIDE + w * 4 + ctg;
    u64* srow1 = srow0 + 8 * SC_STRIDE;
    const u64* bb0 = wbuf + gr * 28;

    float rs0 = 0.f, rs1 = 0.f;
    issueK(0);
    issueK(1);

#pragma unroll 1
    for (int c = 0; c < 16; c++) {
        if (c < 15) cpa_wait<1>(); else cpa_wait<0>();
        __syncwarp();
        const u64* bb = bb0 + ((c & 1) ? KSTG : 0);

        u64 B0[3], B1[3];
#pragma unroll
        for (int g = 0; g < 3; g++) {
            B0[g] = bb[g * 8 + ctg];
            B1[g] = bb[g * 8 + 4 + ctg];
        }
        __syncwarp();
        if (c < 14) issueK(c + 2);

        float4 acc[3];
#pragma unroll
        for (int g = 0; g < 3; g++) acc[g] = make_float4(0.f, 0.f, 0.f, 0.f);
#pragma unroll
        for (int g = 0; g < 3; g++) {
            uint32_t bh0 = (uint32_t)B0[g], bh1 = (uint32_t)B1[g];
            uint32_t bl0 = (uint32_t)(B0[g] >> 32), bl1 = (uint32_t)(B1[g] >> 32);
            mma_bf16(acc[g], Ah[g], bh0, bh1);
            mma_bf16(acc[g], Ah[g], bl0, bl1);
            mma_bf16(acc[g], Al[g], bh0, bh1);
        }

        float4 c1 = acc[0], c2 = acc[1], c3 = acc[2];
        float fr, fi, p0, p1, p2, p3;
        fr = c1.x + c2.x; fi = c3.x - c1.x + c2.x; p0 = fr * fr + fi * fi;
        fr = c1.y + c2.y; fi = c3.y - c1.y + c2.y; p1 = fr * fr + fi * fi;
        fr = c1.z + c2.z; fi = c3.z - c1.z + c2.z; p2 = fr * fr + fi * fi;
        fr = c1.w + c2.w; fi = c3.w - c1.w + c2.w; p3 = fr * fr + fi * fi;

        uint32_t h01 = bfpack(p0, p1);
        uint32_t h23 = bfpack(p2, p3);
        uint32_t l01 = bfpack(p0 - bflowf(h01), p1 - bfhighf(h01));
        uint32_t l23 = bfpack(p2 - bflowf(h23), p3 - bfhighf(h23));
        srow0[c * 32] = (u64)h01 | ((u64)l01 << 32);
        srow1[c * 32] = (u64)h23 | ((u64)l23 << 32);
        rs0 += p0 + p1; rs1 += p2 + p3;
    }

    // ---- rowsums ----
    rs0 += __shfl_xor_sync(0xFFFFFFFFu, rs0, 1);
    rs0 += __shfl_xor_sync(0xFFFFFFFFu, rs0, 2);
    rs1 += __shfl_xor_sync(0xFFFFFFFFu, rs1, 1);
    rs1 += __shfl_xor_sync(0xFFFFFFFFu, rs1, 2);
    if (ctg == 0) { sred[w][gr] = rs0; sred[w][gr + 8] = rs1; }
    __syncthreads();

    // ---- V pipeline (hoisted addresses), prologue overlaps weights write ----
    const u64* vt = g_vTi + (size_t)bh * 32768;
    const int vr0 = lane >> 4, vf0 = lane & 15;    // t tiles: r = vr0 + 2t
    uint32_t vd[4];
    const u64* vs[4];
#pragma unroll
    for (int t = 0; t < 4; t++) {
        int r = vr0 + 2 * t;
        vd[t] = wsa + (uint32_t)(r * 36 + vf0 * 2) * 8;
        vs[t] = vt + (size_t)(w * 8 + r) * 512 + vf0 * 2;
    }
    auto issueV = [&](int c) {
        const uint32_t so = (c & 1) ? (uint32_t)(288 * 8) : 0u;
        const int go = c * 32;
        cpa16s(vd[0] + so, vs[0] + go);
        cpa16s(vd[1] + so, vs[1] + go);
        cpa16s(vd[2] + so, vs[2] + go);
        cpa16s(vd[3] + so, vs[3] + go);
        cpa_commit();
    };
    issueV(0);
    issueV(1);

    if (tid < 16) {
        float s = 0.f;
#pragma unroll
        for (int ww = 0; ww < 8; ww++) s += sred[ww][tid];
        sinv[tid] = 1.0f / (s + 1e-6f);
    }
    __syncthreads();

    // ---- phase B: single normalized weights pass ----
    {
        float2* wout = (float2*)(out + (size_t)CTX_ELEMS + ((size_t)bh * 1024 + l0) * 1024);
#pragma unroll 8
        for (int i = tid; i < 8192; i += 256) {
            int row = i >> 9, pr = i & 511;
            u64 v = scores[row * SC_STRIDE + pr];
            uint32_t hv = (uint32_t)v, lv = (uint32_t)(v >> 32);
            float iv = sinv[row];
            wout[(size_t)row * 512 + pr] =
                make_float2((bflowf(hv) + bflowf(lv)) * iv,
                            (bfhighf(hv) + bfhighf(lv)) * iv);
        }
    }

    // ---- phase C: context (warp = d-octet) ----
    float4 aHH = make_float4(0.f, 0.f, 0.f, 0.f);
    float4 aHL = make_float4(0.f, 0.f, 0.f, 0.f);
    float4 aLH = make_float4(0.f, 0.f, 0.f, 0.f);
    const u64* vbb0 = wbuf + gr * 36;
    const u64* sC0 = scores + gr * SC_STRIDE + ctg;
    const u64* sC1 = sC0 + 8 * SC_STRIDE;

#pragma unroll 1
    for (int c = 0; c < 16; c++) {
        if (c < 15) cpa_wait<1>(); else cpa_wait<0>();
        __syncwarp();
        const u64* vbb = vbb0 + ((c & 1) ? 288 : 0);

        u64 vv[4][2];
#pragma unroll
        for (int kk = 0; kk < 4; kk++) {
            vv[kk][0] = vbb[kk * 8 + ctg];
            vv[kk][1] = vbb[kk * 8 + 4 + ctg];
        }
        __syncwarp();
        if (c < 14) issueV(c + 2);

#pragma unroll
        for (int kk = 0; kk < 4; kk++) {
            int base = c * 32 + kk * 8;
            u64 s0 = sC0[base];
            u64 s1 = sC1[base];
            u64 s2 = sC0[base + 4];
            u64 s3 = sC1[base + 4];
            uint32_t aH[4] = {(uint32_t)s0, (uint32_t)s1, (uint32_t)s2, (uint32_t)s3};
            uint32_t aL[4] = {(uint32_t)(s0 >> 32), (uint32_t)(s1 >> 32),
                              (uint32_t)(s2 >> 32), (uint32_t)(s3 >> 32)};
            uint32_t bh0 = (uint32_t)vv[kk][0], bh1 = (uint32_t)vv[kk][1];
            uint32_t bl0 = (uint32_t)(vv[kk][0] >> 32), bl1 = (uint32_t)(vv[kk][1] >> 32);

            mma_bf16(aHH, aH, bh0, bh1);
            mma_bf16(aHL, aH, bl0, bl1);
            mma_bf16(aLH, aL, bh0, bh1);
        }
    }

    {
        float4 cc = make_float4(aHH.x + aHL.x + aLH.x, aHH.y + aHL.y + aLH.y,
                                aHH.z + aHL.z + aLH.z, aHH.w + aHL.w + aLH.w);
        float ivt = sinv[gr], ivb = sinv[gr + 8];
        int lt = l0 + gr, lb = lt + 8;
        int d = w * 8 + 2 * ctg;
        *(float2*)&out[((size_t)((b * 1024 + lt) * 8 + h)) * 64 + d]
            = make_float2(cc.x * ivt, cc.y * ivt);
        *(float2*)&out[((size_t)((b * 1024 + lb) * 8 + h)) * 64 + d]
            = make_float2(cc.z * ivb, cc.w * ivb);
    }
}

// ======================================================================
extern "C" void kernel_launch(void* const* d_in, const int* in_sizes, int n_in,
                              void* d_out, int out_size)
{
    (void)in_sizes; (void)n_in; (void)out_size;
    const float* q  = (const float*)d_in[0];
    const float* k  = (const float*)d_in[1];
    const float* v  = (const float*)d_in[2];
    const float* wq = (const float*)d_in[3];
    const float* bq = (const float*)d_in[4];
    const float* wk = (const float*)d_in[5];
    const float* bk = (const float*)d_in[6];
    float* out = (float*)d_out;

    cudaFuncSetAttribute(prep_kernel, cudaFuncAttributeMaxDynamicSharedMemorySize, PREP_SMEM);
    cudaFuncSetAttribute(attn_fused,  cudaFuncAttributeMaxDynamicSharedMemorySize, SMEM_BYTES);

    prep_kernel<<<768, 256, PREP_SMEM>>>(q, k, v, wq, bq, wk, bk);
    attn_fused<<<dim3(64, BHN), 256, SMEM_BYTES>>>(out);
}